// round 2
// baseline (speedup 1.0000x reference)
#include <cuda_runtime.h>
#include <cuda_fp16.h>
#include <cstdint>

#define NNODE 8192
#define INDIM 256
#define HID   128

// 2 MB scratch: Ht16[c][j] = H[j][c] in fp16 (round-to-nearest)
__device__ __half g_Ht16[HID * NNODE];

// ---------------------------------------------------------------------------
// Kernel 1: Ht16[c][j] = fp16( sum_d W[c,d]*x[j,d] + b[c] )
// 128 threads (c), 16 nodes per block.
// ---------------------------------------------------------------------------
__global__ __launch_bounds__(128) void ht_kernel(const float* __restrict__ x,
                                                 const float* __restrict__ W,
                                                 const float* __restrict__ b) {
    __shared__ float4 xs[16][64];  // 16 nodes x 256 dims
    const int c  = threadIdx.x;
    const int j0 = blockIdx.x * 16;

    const float4* xg = reinterpret_cast<const float4*>(x + (size_t)j0 * INDIM);
#pragma unroll
    for (int t = 0; t < 8; t++) {
        int idx = c + t * 128;
        int jj = idx >> 6, d4 = idx & 63;
        xs[jj][d4] = xg[jj * 64 + d4];
    }
    __syncthreads();

    float acc[16];
#pragma unroll
    for (int jj = 0; jj < 16; jj++) acc[jj] = 0.f;

    const float4* wg = reinterpret_cast<const float4*>(W + (size_t)c * INDIM);
#pragma unroll 4
    for (int d4 = 0; d4 < 64; d4++) {
        float4 w4 = wg[d4];
#pragma unroll
        for (int jj = 0; jj < 16; jj++) {
            float4 x4 = xs[jj][d4];
            acc[jj] += w4.x * x4.x;
            acc[jj] += w4.y * x4.y;
            acc[jj] += w4.z * x4.z;
            acc[jj] += w4.w * x4.w;
        }
    }

    const float bc = b[c];
#pragma unroll
    for (int jj = 0; jj < 16; jj++)
        g_Ht16[(size_t)c * NNODE + (j0 + jj)] = __float2half_rn(acc[jj] + bc);
}

// ---------------------------------------------------------------------------
// Kernel 2: out[8192,128] = G @ H via mma.sync.m16n8k16 f16 (fp32 accum)
//   Grid 128 CTAs, tile M=64 N=128, KT=32, 4-stage smem pipeline.
//   A (G): LDG.128 fp32 -> x1024 -> fp16 -> STS (3-deep reg pipeline)
//   B (Ht16): cp.async.cg from L2-resident scratch
// ---------------------------------------------------------------------------
static constexpr int S           = 4;
static constexpr int KT          = 32;
static constexpr int NS          = NNODE / KT;      // 256
static constexpr int ROW_STRIDE  = 80;              // bytes (64B data + 16B pad)
static constexpr int A_BYTES     = 64 * ROW_STRIDE; // 5120
static constexpr int STAGE_BYTES = A_BYTES + 128 * ROW_STRIDE; // 15360
static constexpr int SMEM_BYTES  = S * STAGE_BYTES; // 61440
#define A_SCALE 1024.0f
#define O_SCALE (1.0f / 1024.0f)

__device__ __forceinline__ void cp_async16(uint32_t smem_dst, const void* gmem_src) {
    asm volatile("cp.async.cg.shared.global [%0], [%1], 16;" :: "r"(smem_dst), "l"(gmem_src));
}
__device__ __forceinline__ uint32_t lds32(uint32_t addr) {
    uint32_t v;
    asm volatile("ld.shared.b32 %0, [%1];" : "=r"(v) : "r"(addr));
    return v;
}
__device__ __forceinline__ void mma16816(float* d, const uint32_t* a, const uint32_t* bfr) {
    asm volatile(
        "mma.sync.aligned.m16n8k16.row.col.f32.f16.f16.f32 "
        "{%0,%1,%2,%3}, {%4,%5,%6,%7}, {%8,%9}, {%0,%1,%2,%3};"
        : "+f"(d[0]), "+f"(d[1]), "+f"(d[2]), "+f"(d[3])
        : "r"(a[0]), "r"(a[1]), "r"(a[2]), "r"(a[3]), "r"(bfr[0]), "r"(bfr[1]));
}

__global__ void __launch_bounds__(256, 1) gemm_kernel(const float* __restrict__ G,
                                                      float* __restrict__ out) {
    extern __shared__ char smem[];
    const uint32_t sbase = (uint32_t)__cvta_generic_to_shared(smem);

    const int tid  = threadIdx.x;
    const int wid  = tid >> 5, lane = tid & 31;
    const int wm   = wid >> 2, wn = wid & 3;     // warp grid 2(M) x 4(N)
    const int g    = lane >> 2, q = lane & 3;
    const int m0   = blockIdx.x * 64;

    // ---- per-thread producer mappings ----
    // A: 512 float4-chunks/stage; thread handles c = tid, tid+256
    const int a_row0 = tid >> 3, a_c80 = tid & 7;           // c = tid
    const int a_row1 = (tid + 256) >> 3, a_c81 = (tid + 256) & 7;
    const float4* a_src0 = reinterpret_cast<const float4*>(G + (size_t)(m0 + a_row0) * NNODE) + a_c80;
    const float4* a_src1 = reinterpret_cast<const float4*>(G + (size_t)(m0 + a_row1) * NNODE) + a_c81;
    const uint32_t a_dst0 = a_row0 * ROW_STRIDE + a_c80 * 8;
    const uint32_t a_dst1 = a_row1 * ROW_STRIDE + a_c81 * 8;
    // B: 512 16B-chunks/stage; thread handles c = tid, tid+256
    const int b_row0 = tid >> 2, b_c160 = tid & 3;
    const int b_row1 = (tid + 256) >> 2, b_c161 = (tid + 256) & 3;
    const __half* b_src0 = g_Ht16 + (size_t)b_row0 * NNODE + b_c160 * 8;
    const __half* b_src1 = g_Ht16 + (size_t)b_row1 * NNODE + b_c161 * 8;
    const uint32_t b_dst0 = A_BYTES + b_row0 * ROW_STRIDE + b_c160 * 16;
    const uint32_t b_dst1 = A_BYTES + b_row1 * ROW_STRIDE + b_c161 * 16;

    float4 abuf[3][2];

#define LDG_A(stage, i)                                                             \
    do {                                                                            \
        int k4 = (stage) * (KT / 4);                                                \
        abuf[i][0] = __ldcs(a_src0 + k4);                                           \
        abuf[i][1] = __ldcs(a_src1 + k4);                                           \
    } while (0)

#define STS_A(slot, i)                                                              \
    do {                                                                            \
        uint32_t sb = sbase + (slot) * STAGE_BYTES;                                 \
        float4 v0 = abuf[i][0];                                                     \
        float4 v1 = abuf[i][1];                                                     \
        __half2 h00 = __floats2half2_rn(v0.x * A_SCALE, v0.y * A_SCALE);            \
        __half2 h01 = __floats2half2_rn(v0.z * A_SCALE, v0.w * A_SCALE);            \
        __half2 h10 = __floats2half2_rn(v1.x * A_SCALE, v1.y * A_SCALE);            \
        __half2 h11 = __floats2half2_rn(v1.z * A_SCALE, v1.w * A_SCALE);            \
        asm volatile("st.shared.v2.b32 [%0], {%1,%2};" ::                           \
            "r"(sb + a_dst0), "r"(*(uint32_t*)&h00), "r"(*(uint32_t*)&h01) : "memory"); \
        asm volatile("st.shared.v2.b32 [%0], {%1,%2};" ::                           \
            "r"(sb + a_dst1), "r"(*(uint32_t*)&h10), "r"(*(uint32_t*)&h11) : "memory"); \
    } while (0)

#define ISSUE_B(stage, slot)                                                        \
    do {                                                                            \
        uint32_t sb = sbase + (slot) * STAGE_BYTES;                                 \
        int kh = (stage) * KT;                                                      \
        cp_async16(sb + b_dst0, b_src0 + kh);                                       \
        cp_async16(sb + b_dst1, b_src1 + kh);                                       \
    } while (0)

    float acc[2][4][4];
#pragma unroll
    for (int mt = 0; mt < 2; mt++)
#pragma unroll
        for (int nt = 0; nt < 4; nt++)
#pragma unroll
            for (int i = 0; i < 4; i++) acc[mt][nt][i] = 0.f;

    // per-warp fragment base offsets (slot-invariant part)
    const uint32_t a_frag_base = sbase + (uint32_t)((wm * 32 + g) * ROW_STRIDE + q * 4);
    const uint32_t b_frag_base = sbase + (uint32_t)(A_BYTES + (wn * 32 + g) * ROW_STRIDE + q * 4);

    // ---- prologue ----
    LDG_A(0, 0);
    LDG_A(1, 1);
    LDG_A(2, 2);
#pragma unroll
    for (int ps = 0; ps < S - 1; ps++) {
        ISSUE_B(ps, ps);
        asm volatile("cp.async.commit_group;" ::: "memory");
    }
    STS_A(0, 0);

    // ---- main loop ----
    for (int s = 0; s < NS; s++) {
        asm volatile("cp.async.wait_group %0;" :: "n"(S - 2) : "memory");
        __syncthreads();

        const uint32_t soff = (uint32_t)((s & 3) * STAGE_BYTES);
#pragma unroll
        for (int kk = 0; kk < 2; kk++) {
            uint32_t af[2][4];
#pragma unroll
            for (int mt = 0; mt < 2; mt++) {
                uint32_t base = a_frag_base + soff + mt * (16 * ROW_STRIDE) + kk * 32;
                af[mt][0] = lds32(base);
                af[mt][1] = lds32(base + 8 * ROW_STRIDE);
                af[mt][2] = lds32(base + 16);
                af[mt][3] = lds32(base + 8 * ROW_STRIDE + 16);
            }
            uint32_t bf[4][2];
#pragma unroll
            for (int nt = 0; nt < 4; nt++) {
                uint32_t base = b_frag_base + soff + nt * (8 * ROW_STRIDE) + kk * 32;
                bf[nt][0] = lds32(base);
                bf[nt][1] = lds32(base + 16);
            }
#pragma unroll
            for (int mt = 0; mt < 2; mt++)
#pragma unroll
                for (int nt = 0; nt < 4; nt++) mma16816(acc[mt][nt], af[mt], bf[nt]);
        }

        if (s + 3 < NS) LDG_A(s + 3, s % 3);
        if (s + 1 < NS) STS_A((s + 1) & 3, (s + 1) % 3);
        if (s + S - 1 < NS) ISSUE_B(s + S - 1, (s + S - 1) & 3);
        asm volatile("cp.async.commit_group;" ::: "memory");
    }

    // ---- epilogue: acc -> out (x 2^-10) ----
#pragma unroll
    for (int mt = 0; mt < 2; mt++) {
#pragma unroll
        for (int nt = 0; nt < 4; nt++) {
            int row = m0 + wm * 32 + mt * 16 + g;
            int col = wn * 32 + nt * 8 + 2 * q;
            float2 v0 = make_float2(acc[mt][nt][0] * O_SCALE, acc[mt][nt][1] * O_SCALE);
            float2 v1 = make_float2(acc[mt][nt][2] * O_SCALE, acc[mt][nt][3] * O_SCALE);
            *reinterpret_cast<float2*>(out + (size_t)row * HID + col) = v0;
            *reinterpret_cast<float2*>(out + (size_t)(row + 8) * HID + col) = v1;
        }
    }
}

// ---------------------------------------------------------------------------
// launch
// ---------------------------------------------------------------------------
extern "C" void kernel_launch(void* const* d_in, const int* in_sizes, int n_in,
                              void* d_out, int out_size) {
    const float* x = nullptr;
    const float* G = nullptr;
    const float* W = nullptr;
    const float* b = nullptr;
    bool g_set = false;
    for (int i = 0; i < n_in; i++) {
        int sz = in_sizes[i];
        if (sz == NNODE * INDIM)       x = (const float*)d_in[i];
        else if (sz == NNODE * NNODE)  { if (!g_set) { G = (const float*)d_in[i]; g_set = true; } }
        else if (sz == HID * INDIM)    W = (const float*)d_in[i];
        else if (sz == HID)            b = (const float*)d_in[i];
    }
    if (!x && n_in > 0) x = (const float*)d_in[0];
    if (!G && n_in > 1) G = (const float*)d_in[1];
    if (!W && n_in > 3) W = (const float*)d_in[3];
    if (!b && n_in > 4) b = (const float*)d_in[4];

    ht_kernel<<<NNODE / 16, 128>>>(x, W, b);

    cudaFuncSetAttribute(gemm_kernel, cudaFuncAttributeMaxDynamicSharedMemorySize, SMEM_BYTES);
    gemm_kernel<<<NNODE / 64, 256, SMEM_BYTES>>>(G, (float*)d_out);
}

// round 3
// speedup vs baseline: 1.1367x; 1.1367x over previous
#include <cuda_runtime.h>
#include <cuda_fp16.h>
#include <cstdint>

#define NNODE 8192
#define INDIM 256
#define HID   128

// 2 MB scratch: Ht16[c][j] = H[j][c] in fp16
__device__ __half g_Ht16[HID * NNODE];

// ---------------------------------------------------------------------------
// mbarrier helpers
// ---------------------------------------------------------------------------
__device__ __forceinline__ void mbar_init(uint32_t a, uint32_t n) {
    asm volatile("mbarrier.init.shared.b64 [%0], %1;" :: "r"(a), "r"(n) : "memory");
}
__device__ __forceinline__ void mbar_arrive(uint32_t a) {
    asm volatile("mbarrier.arrive.release.cta.shared::cta.b64 _, [%0];" :: "r"(a) : "memory");
}
__device__ __forceinline__ void mbar_wait(uint32_t a, uint32_t parity) {
    asm volatile(
        "{\n\t.reg .pred P;\n\t"
        "WL_%=:\n\t"
        "mbarrier.try_wait.parity.acquire.cta.shared::cta.b64 P, [%0], %1, 0x989680;\n\t"
        "@P bra.uni WD_%=;\n\t"
        "bra.uni WL_%=;\n\t"
        "WD_%=:\n\t}"
        :: "r"(a), "r"(parity) : "memory");
}
__device__ __forceinline__ void cp_async16(uint32_t smem_dst, const void* gmem_src) {
    asm volatile("cp.async.cg.shared.global [%0], [%1], 16;" :: "r"(smem_dst), "l"(gmem_src));
}
__device__ __forceinline__ uint32_t lds32(uint32_t addr) {
    uint32_t v;
    asm volatile("ld.shared.b32 %0, [%1];" : "=r"(v) : "r"(addr));
    return v;
}
__device__ __forceinline__ void mma16816(float* d, const uint32_t* a, const uint32_t* bfr) {
    asm volatile(
        "mma.sync.aligned.m16n8k16.row.col.f32.f16.f16.f32 "
        "{%0,%1,%2,%3}, {%4,%5,%6,%7}, {%8,%9}, {%0,%1,%2,%3};"
        : "+f"(d[0]), "+f"(d[1]), "+f"(d[2]), "+f"(d[3])
        : "r"(a[0]), "r"(a[1]), "r"(a[2]), "r"(a[3]), "r"(bfr[0]), "r"(bfr[1]));
}

// ---------------------------------------------------------------------------
// Kernel 1: Ht16[c][j] = fp16( sum_d W[c,d]*x[j,d] + b[c] )
// ---------------------------------------------------------------------------
__global__ __launch_bounds__(128) void ht_kernel(const float* __restrict__ x,
                                                 const float* __restrict__ W,
                                                 const float* __restrict__ b) {
    __shared__ float4 xs[16][64];
    const int c  = threadIdx.x;
    const int j0 = blockIdx.x * 16;

    const float4* xg = reinterpret_cast<const float4*>(x + (size_t)j0 * INDIM);
#pragma unroll
    for (int t = 0; t < 8; t++) {
        int idx = c + t * 128;
        int jj = idx >> 6, d4 = idx & 63;
        xs[jj][d4] = xg[jj * 64 + d4];
    }
    __syncthreads();

    float acc[16];
#pragma unroll
    for (int jj = 0; jj < 16; jj++) acc[jj] = 0.f;

    const float4* wg = reinterpret_cast<const float4*>(W + (size_t)c * INDIM);
#pragma unroll 1
    for (int dc = 0; dc < 64; dc += 8) {
        float4 wb[8];
#pragma unroll
        for (int i = 0; i < 8; i++) wb[i] = __ldg(wg + dc + i);
#pragma unroll
        for (int i = 0; i < 8; i++) {
            float4 w4 = wb[i];
#pragma unroll
            for (int jj = 0; jj < 16; jj++) {
                float4 x4 = xs[jj][dc + i];
                acc[jj] += w4.x * x4.x;
                acc[jj] += w4.y * x4.y;
                acc[jj] += w4.z * x4.z;
                acc[jj] += w4.w * x4.w;
            }
        }
    }

    const float bc = b[c];
    uint32_t hh[8];
#pragma unroll
    for (int j = 0; j < 8; j++) {
        __half2 h = __floats2half2_rn(acc[2 * j] + bc, acc[2 * j + 1] + bc);
        hh[j] = *reinterpret_cast<uint32_t*>(&h);
    }
    uint4* dst = reinterpret_cast<uint4*>(g_Ht16 + (size_t)c * NNODE + j0);
    dst[0] = make_uint4(hh[0], hh[1], hh[2], hh[3]);
    dst[1] = make_uint4(hh[4], hh[5], hh[6], hh[7]);
}

// ---------------------------------------------------------------------------
// Kernel 2: out = G @ H, warp-specialized. CTA: 512 thr, M=64, N=128, KT=32.
//   warps 0-7  producers: A = G fp32 -> fp16*1024 -> STS; B = cp.async Ht16
//   warps 8-15 consumers: LDS fragments + mma.sync m16n8k16
// ---------------------------------------------------------------------------
static constexpr int S        = 8;               // ring stages
static constexpr int KT       = 32;
static constexpr int NS       = NNODE / KT;      // 256
static constexpr int RS       = 80;              // bytes/row (64B data + 16 pad)
static constexpr int A_BYTES  = 64 * RS;         // 5120
static constexpr int STAGE    = A_BYTES + 128 * RS;  // 15360
static constexpr int TILE0    = 1024;            // ctrl region
static constexpr int SMEM_BYTES = TILE0 + S * STAGE; // 123904
#define A_SCALE 1024.0f
#define O_SCALE (1.0f / 1024.0f)

__global__ void __launch_bounds__(512, 1) gemm_kernel(const float* __restrict__ G,
                                                      float* __restrict__ out) {
    extern __shared__ char smem[];
    const uint32_t sb    = (uint32_t)__cvta_generic_to_shared(smem);
    const uint32_t full0  = sb;        // 8 x 8B
    const uint32_t empty0 = sb + 64;   // 8 x 8B
    const uint32_t tiles  = sb + TILE0;

    const int tid = threadIdx.x;
    const int wid = tid >> 5, lane = tid & 31;
    const int m0  = blockIdx.x * 64;

    if (tid == 0) {
#pragma unroll
        for (int s = 0; s < S; s++) {
            mbar_init(full0 + s * 8, 256);   // producers
            mbar_init(empty0 + s * 8, 256);  // consumers
        }
    }
    __syncthreads();

    if (wid < 8) {
        // ================= producers =================
        const int pt  = tid;            // 0..255
        const int pt1 = pt + 256;
        const int a_row0 = pt >> 3, a_c0 = pt & 7;
        const int a_row1 = pt1 >> 3, a_c1 = pt1 & 7;
        const float4* a_src0 = reinterpret_cast<const float4*>(G + (size_t)(m0 + a_row0) * NNODE) + a_c0;
        const float4* a_src1 = reinterpret_cast<const float4*>(G + (size_t)(m0 + a_row1) * NNODE) + a_c1;
        const uint32_t a_dst0 = (uint32_t)(a_row0 * RS + a_c0 * 8);
        const uint32_t a_dst1 = (uint32_t)(a_row1 * RS + a_c1 * 8);
        const int b_row0 = pt >> 2, b_c0 = pt & 3;
        const int b_row1 = pt1 >> 2, b_c1 = pt1 & 3;
        const __half* b_src0 = g_Ht16 + (size_t)b_row0 * NNODE + b_c0 * 8;
        const __half* b_src1 = g_Ht16 + (size_t)b_row1 * NNODE + b_c1 * 8;
        const uint32_t b_dst0 = (uint32_t)(A_BYTES + b_row0 * RS + b_c0 * 16);
        const uint32_t b_dst1 = (uint32_t)(A_BYTES + b_row1 * RS + b_c1 * 16);

        float4 ab[3][2];
        ab[0][0] = __ldcs(a_src0);       ab[0][1] = __ldcs(a_src1);
        ab[1][0] = __ldcs(a_src0 + 8);   ab[1][1] = __ldcs(a_src1 + 8);
        ab[2][0] = __ldcs(a_src0 + 16);  ab[2][1] = __ldcs(a_src1 + 16);

        int slot = 0, lap = 0, aslot = 0;
        for (int s = 0; s < NS; s++) {
            if (lap > 0) mbar_wait(empty0 + slot * 8, (lap - 1) & 1);
            const uint32_t st = tiles + slot * STAGE;
            // B via cp.async (L2-resident Ht16)
            cp_async16(st + b_dst0, b_src0 + s * KT);
            cp_async16(st + b_dst1, b_src1 + s * KT);
            asm volatile("cp.async.commit_group;" ::: "memory");
            // A: cvt + STS for stage s
            const int ib = s % 3;
            {
                float4 v0 = ab[ib][0], v1 = ab[ib][1];
                __half2 h00 = __floats2half2_rn(v0.x * A_SCALE, v0.y * A_SCALE);
                __half2 h01 = __floats2half2_rn(v0.z * A_SCALE, v0.w * A_SCALE);
                __half2 h10 = __floats2half2_rn(v1.x * A_SCALE, v1.y * A_SCALE);
                __half2 h11 = __floats2half2_rn(v1.z * A_SCALE, v1.w * A_SCALE);
                asm volatile("st.shared.v2.b32 [%0], {%1,%2};" ::
                    "r"(st + a_dst0), "r"(*(uint32_t*)&h00), "r"(*(uint32_t*)&h01) : "memory");
                asm volatile("st.shared.v2.b32 [%0], {%1,%2};" ::
                    "r"(st + a_dst1), "r"(*(uint32_t*)&h10), "r"(*(uint32_t*)&h11) : "memory");
            }
            // prefetch A for stage s+3
            if (s + 3 < NS) {
                ab[ib][0] = __ldcs(a_src0 + (s + 3) * 8);
                ab[ib][1] = __ldcs(a_src1 + (s + 3) * 8);
            }
            // lagged full-arrival for stage s-2
            if (s >= 2) {
                asm volatile("cp.async.wait_group 2;" ::: "memory");
                mbar_arrive(full0 + aslot * 8);
                if (++aslot == S) aslot = 0;
            }
            if (++slot == S) { slot = 0; lap++; }
        }
        asm volatile("cp.async.wait_group 0;" ::: "memory");
        mbar_arrive(full0 + aslot * 8);
        if (++aslot == S) aslot = 0;
        mbar_arrive(full0 + aslot * 8);
    } else {
        // ================= consumers =================
        const int cw = wid - 8;                    // 0..7
        const int wm = cw >> 2, wn = cw & 3;       // 2(M) x 4(N) warp grid
        const int g = lane >> 2, q = lane & 3;
        const uint32_t a_base = tiles + (uint32_t)((wm * 32 + g) * RS + q * 4);
        const uint32_t b_base = tiles + (uint32_t)(A_BYTES + (wn * 32 + g) * RS + q * 4);

        float acc[2][4][4];
#pragma unroll
        for (int mt = 0; mt < 2; mt++)
#pragma unroll
            for (int nt = 0; nt < 4; nt++)
#pragma unroll
                for (int i = 0; i < 4; i++) acc[mt][nt][i] = 0.f;

        int slot = 0, lap = 0;
        for (int s = 0; s < NS; s++) {
            mbar_wait(full0 + slot * 8, lap & 1);
            const uint32_t soff = (uint32_t)(slot * STAGE);
#pragma unroll
            for (int kk = 0; kk < 2; kk++) {
                uint32_t af[2][4];
#pragma unroll
                for (int mt = 0; mt < 2; mt++) {
                    uint32_t base = a_base + soff + mt * (16 * RS) + kk * 32;
                    af[mt][0] = lds32(base);
                    af[mt][1] = lds32(base + 8 * RS);
                    af[mt][2] = lds32(base + 16);
                    af[mt][3] = lds32(base + 8 * RS + 16);
                }
                uint32_t bf[4][2];
#pragma unroll
                for (int nt = 0; nt < 4; nt++) {
                    uint32_t base = b_base + soff + nt * (8 * RS) + kk * 32;
                    bf[nt][0] = lds32(base);
                    bf[nt][1] = lds32(base + 16);
                }
#pragma unroll
                for (int mt = 0; mt < 2; mt++)
#pragma unroll
                    for (int nt = 0; nt < 4; nt++) mma16816(acc[mt][nt], af[mt], bf[nt]);
            }
            mbar_arrive(empty0 + slot * 8);
            if (++slot == S) { slot = 0; lap ^= 1; }
        }

        // epilogue
#pragma unroll
        for (int mt = 0; mt < 2; mt++) {
#pragma unroll
            for (int nt = 0; nt < 4; nt++) {
                int row = m0 + wm * 32 + mt * 16 + g;
                int col = wn * 32 + nt * 8 + 2 * q;
                float2 v0 = make_float2(acc[mt][nt][0] * O_SCALE, acc[mt][nt][1] * O_SCALE);
                float2 v1 = make_float2(acc[mt][nt][2] * O_SCALE, acc[mt][nt][3] * O_SCALE);
                *reinterpret_cast<float2*>(out + (size_t)row * HID + col) = v0;
                *reinterpret_cast<float2*>(out + (size_t)(row + 8) * HID + col) = v1;
            }
        }
    }
}

// ---------------------------------------------------------------------------
// launch
// ---------------------------------------------------------------------------
extern "C" void kernel_launch(void* const* d_in, const int* in_sizes, int n_in,
                              void* d_out, int out_size) {
    const float* x = nullptr;
    const float* G = nullptr;
    const float* W = nullptr;
    const float* b = nullptr;
    bool g_set = false;
    for (int i = 0; i < n_in; i++) {
        int sz = in_sizes[i];
        if (sz == NNODE * INDIM)       x = (const float*)d_in[i];
        else if (sz == NNODE * NNODE)  { if (!g_set) { G = (const float*)d_in[i]; g_set = true; } }
        else if (sz == HID * INDIM)    W = (const float*)d_in[i];
        else if (sz == HID)            b = (const float*)d_in[i];
    }
    if (!x && n_in > 0) x = (const float*)d_in[0];
    if (!G && n_in > 1) G = (const float*)d_in[1];
    if (!W && n_in > 3) W = (const float*)d_in[3];
    if (!b && n_in > 4) b = (const float*)d_in[4];

    ht_kernel<<<NNODE / 16, 128>>>(x, W, b);

    cudaFuncSetAttribute(gemm_kernel, cudaFuncAttributeMaxDynamicSharedMemorySize, SMEM_BYTES);
    gemm_kernel<<<NNODE / 64, 512, SMEM_BYTES>>>(G, (float*)d_out);
}

// round 4
// speedup vs baseline: 1.7669x; 1.5544x over previous
#include <cuda_runtime.h>
#include <cuda_fp16.h>
#include <cstdint>

#define NNODE 8192
#define INDIM 256
#define HID   128

__device__ __half g_Ht16[HID * NNODE];

// ---------------------------------------------------------------------------
// helpers
// ---------------------------------------------------------------------------
__device__ __forceinline__ void mbar_init(uint32_t a, uint32_t n) {
    asm volatile("mbarrier.init.shared.b64 [%0], %1;" :: "r"(a), "r"(n) : "memory");
}
__device__ __forceinline__ void mbar_arrive(uint32_t a) {
    asm volatile("mbarrier.arrive.release.cta.shared::cta.b64 _, [%0];" :: "r"(a) : "memory");
}
__device__ __forceinline__ void mbar_wait(uint32_t a, uint32_t parity) {
    asm volatile(
        "{\n\t.reg .pred P;\n\t"
        "WL_%=:\n\t"
        "mbarrier.try_wait.parity.acquire.cta.shared::cta.b64 P, [%0], %1, 0x989680;\n\t"
        "@P bra.uni WD_%=;\n\t"
        "bra.uni WL_%=;\n\t"
        "WD_%=:\n\t}"
        :: "r"(a), "r"(parity) : "memory");
}
__device__ __forceinline__ void cp_async16(uint32_t smem_dst, const void* gmem_src) {
    asm volatile("cp.async.cg.shared.global [%0], [%1], 16;" :: "r"(smem_dst), "l"(gmem_src));
}
__device__ __forceinline__ uint32_t lds32(uint32_t addr) {
    uint32_t v;
    asm volatile("ld.shared.b32 %0, [%1];" : "=r"(v) : "r"(addr));
    return v;
}
__device__ __forceinline__ void mma16816(float* d, const uint32_t* a, const uint32_t* bfr) {
    asm volatile(
        "mma.sync.aligned.m16n8k16.row.col.f32.f16.f16.f32 "
        "{%0,%1,%2,%3}, {%4,%5,%6,%7}, {%8,%9}, {%0,%1,%2,%3};"
        : "+f"(d[0]), "+f"(d[1]), "+f"(d[2]), "+f"(d[3])
        : "r"(a[0]), "r"(a[1]), "r"(a[2]), "r"(a[3]), "r"(bfr[0]), "r"(bfr[1]));
}

// ---------------------------------------------------------------------------
// Kernel 1: Ht16[c][j] = fp16( sum_d W[c,d]*x[j,d] + b[c] )
// ---------------------------------------------------------------------------
__global__ __launch_bounds__(128) void ht_kernel(const float* __restrict__ x,
                                                 const float* __restrict__ W,
                                                 const float* __restrict__ b) {
    __shared__ float4 xs[16][64];
    const int c  = threadIdx.x;
    const int j0 = blockIdx.x * 16;

    const float4* xg = reinterpret_cast<const float4*>(x + (size_t)j0 * INDIM);
#pragma unroll
    for (int t = 0; t < 8; t++) {
        int idx = c + t * 128;
        int jj = idx >> 6, d4 = idx & 63;
        xs[jj][d4] = xg[jj * 64 + d4];
    }
    __syncthreads();

    float acc[16];
#pragma unroll
    for (int jj = 0; jj < 16; jj++) acc[jj] = 0.f;

    const float4* wg = reinterpret_cast<const float4*>(W + (size_t)c * INDIM);
#pragma unroll 1
    for (int dc = 0; dc < 64; dc += 8) {
        float4 wb[8];
#pragma unroll
        for (int i = 0; i < 8; i++) wb[i] = __ldg(wg + dc + i);
#pragma unroll
        for (int i = 0; i < 8; i++) {
            float4 w4 = wb[i];
#pragma unroll
            for (int jj = 0; jj < 16; jj++) {
                float4 x4 = xs[jj][dc + i];
                acc[jj] += w4.x * x4.x;
                acc[jj] += w4.y * x4.y;
                acc[jj] += w4.z * x4.z;
                acc[jj] += w4.w * x4.w;
            }
        }
    }

    const float bc = b[c];
    uint32_t hh[8];
#pragma unroll
    for (int j = 0; j < 8; j++) {
        __half2 h = __floats2half2_rn(acc[2 * j] + bc, acc[2 * j + 1] + bc);
        hh[j] = *reinterpret_cast<uint32_t*>(&h);
    }
    uint4* dst = reinterpret_cast<uint4*>(g_Ht16 + (size_t)c * NNODE + j0);
    dst[0] = make_uint4(hh[0], hh[1], hh[2], hh[3]);
    dst[1] = make_uint4(hh[4], hh[5], hh[6], hh[7]);
}

// ---------------------------------------------------------------------------
// Kernel 2: out = G @ H. 512 thr/CTA, M=64, N=128, KT=64, 5-stage ring.
//   warps 0-7 producers (A: LDG fp32 depth-3 -> cvt*1024 -> STS; B: cp.async)
//   warps 8-15 consumers: grid 2(M) x 2(N) x 2(Ksplit), smem reduce at end
//   Elected per-warp mbarrier arrivals (count 8 / 8).
// ---------------------------------------------------------------------------
static constexpr int S       = 5;
static constexpr int KT      = 64;
static constexpr int NS      = NNODE / KT;     // 128
static constexpr int RSA     = 144;            // A row stride bytes (128B data + 16 pad)
static constexpr int RSB     = 144;            // B row stride bytes
static constexpr int A_SM    = 64 * RSA;       // 9216
static constexpr int B_SM    = 128 * RSB;      // 18432
static constexpr int STAGE   = A_SM + B_SM;    // 27648
static constexpr int TILE0   = 1024;
static constexpr int SMEM_BYTES = TILE0 + S * STAGE;  // 139264
#define A_SCALE 1024.0f
#define O_SCALE (1.0f / 1024.0f)

__global__ void __launch_bounds__(512, 1) gemm_kernel(const float* __restrict__ G,
                                                      float* __restrict__ out) {
    extern __shared__ char smem[];
    const uint32_t sb     = (uint32_t)__cvta_generic_to_shared(smem);
    const uint32_t full0  = sb;
    const uint32_t empty0 = sb + 64;
    const uint32_t tiles  = sb + TILE0;

    const int tid = threadIdx.x;
    const int wid = tid >> 5, lane = tid & 31;
    const int m0  = blockIdx.x * 64;

    if (tid == 0) {
#pragma unroll
        for (int s = 0; s < S; s++) {
            mbar_init(full0 + s * 8, 8);   // 8 producer warps, elected arrive
            mbar_init(empty0 + s * 8, 8);  // 8 consumer warps, elected arrive
        }
    }
    __syncthreads();

    if (wid < 8) {
        // ============ producers ============
        const int pt = tid;                       // 0..255
        const int r0 = pt >> 4, c16 = pt & 15;    // A: rows r0+16i, float4 col c16
        const int br0 = pt >> 3, c8 = pt & 7;     // B: rows br0+32i, 16B col c8

        const float4* a_src[4];
        uint32_t a_dst[4];
#pragma unroll
        for (int i = 0; i < 4; i++) {
            a_src[i] = reinterpret_cast<const float4*>(G + (size_t)(m0 + r0 + 16 * i) * NNODE) + c16;
            a_dst[i] = (uint32_t)((r0 + 16 * i) * RSA + c16 * 8);
        }
        const __half* b_src[4];
        uint32_t b_dst[4];
#pragma unroll
        for (int i = 0; i < 4; i++) {
            b_src[i] = g_Ht16 + (size_t)(br0 + 32 * i) * NNODE + c8 * 8;
            b_dst[i] = (uint32_t)(A_SM + (br0 + 32 * i) * RSB + c8 * 16);
        }

        float4 buf[3][4];
#pragma unroll
        for (int j = 0; j < 3; j++)
#pragma unroll
            for (int i = 0; i < 4; i++) buf[j][i] = __ldcs(a_src[i] + j * 16);

        int slot = 0, lap = 0, aslot = 0;
        for (int s = 0; s < NS; s++) {
            if (lap > 0) mbar_wait(empty0 + slot * 8, (lap - 1) & 1);
            const uint32_t st = tiles + slot * STAGE;
            // B cp.async
#pragma unroll
            for (int i = 0; i < 4; i++) cp_async16(st + b_dst[i], b_src[i] + s * KT);
            asm volatile("cp.async.commit_group;" ::: "memory");
            // A cvt + STS from buffer loaded 3 stages ago
            const int ib = s % 3;
#pragma unroll
            for (int i = 0; i < 4; i++) {
                float4 v = buf[ib][i];
                __half2 h0 = __floats2half2_rn(v.x * A_SCALE, v.y * A_SCALE);
                __half2 h1 = __floats2half2_rn(v.z * A_SCALE, v.w * A_SCALE);
                asm volatile("st.shared.v2.b32 [%0], {%1,%2};" ::
                    "r"(st + a_dst[i]), "r"(*(uint32_t*)&h0), "r"(*(uint32_t*)&h1) : "memory");
            }
            // prefetch A for stage s+3
            if (s + 3 < NS) {
#pragma unroll
                for (int i = 0; i < 4; i++) buf[ib][i] = __ldcs(a_src[i] + (s + 3) * 16);
            }
            // lagged full-arrival for stage s-2 (elected)
            if (s >= 2) {
                asm volatile("cp.async.wait_group 2;" ::: "memory");
                __syncwarp();
                if (lane == 0) mbar_arrive(full0 + aslot * 8);
                if (++aslot == S) aslot = 0;
            }
            if (++slot == S) { slot = 0; lap++; }
        }
        asm volatile("cp.async.wait_group 0;" ::: "memory");
        __syncwarp();
        if (lane == 0) {
            mbar_arrive(full0 + aslot * 8);
            int a2 = aslot + 1; if (a2 == S) a2 = 0;
            mbar_arrive(full0 + a2 * 8);
        }
        __syncthreads();  // (1) partials being stored by km=1 consumers
        __syncthreads();  // (2) reduction done
    } else {
        // ============ consumers ============
        const int cw = wid - 8;                    // 0..7
        const int km = cw >> 2;                    // k-split half
        const int wm = (cw >> 1) & 1, wn = cw & 1; // 2(M) x 2(N)
        const int g = lane >> 2, q = lane & 3;
        const uint32_t a_base = tiles + (uint32_t)((wm * 32 + g) * RSA + q * 4);
        const uint32_t b_base = tiles + (uint32_t)(A_SM + (wn * 64 + g) * RSB + q * 4);

        float acc[2][8][4];
#pragma unroll
        for (int mt = 0; mt < 2; mt++)
#pragma unroll
            for (int nt = 0; nt < 8; nt++)
#pragma unroll
                for (int i = 0; i < 4; i++) acc[mt][nt][i] = 0.f;

        int slot = 0, lap = 0;
        for (int s = 0; s < NS; s++) {
            mbar_wait(full0 + slot * 8, lap & 1);
            const uint32_t soff = (uint32_t)(slot * STAGE);
#pragma unroll
            for (int kc = 0; kc < 2; kc++) {
                const uint32_t kb = (uint32_t)((2 * km + kc) * 32);
                uint32_t af[2][4];
#pragma unroll
                for (int mt = 0; mt < 2; mt++) {
                    uint32_t base = a_base + soff + mt * (16 * RSA) + kb;
                    af[mt][0] = lds32(base);
                    af[mt][1] = lds32(base + 8 * RSA);
                    af[mt][2] = lds32(base + 16);
                    af[mt][3] = lds32(base + 8 * RSA + 16);
                }
                uint32_t bf[8][2];
#pragma unroll
                for (int nt = 0; nt < 8; nt++) {
                    uint32_t base = b_base + soff + nt * (8 * RSB) + kb;
                    bf[nt][0] = lds32(base);
                    bf[nt][1] = lds32(base + 16);
                }
#pragma unroll
                for (int mt = 0; mt < 2; mt++)
#pragma unroll
                    for (int nt = 0; nt < 8; nt++) mma16816(acc[mt][nt], af[mt], bf[nt]);
            }
            __syncwarp();
            if (lane == 0) mbar_arrive(empty0 + slot * 8);
            if (++slot == S) { slot = 0; lap ^= 1; }
        }

        // ---- K-split reduction + epilogue ----
        const uint32_t part = tiles + (uint32_t)(((cw & 3) * 32 + lane) * 272);
        __syncthreads();  // (1) all consumers done with ring; producers done
        if (km == 1) {
            float* pa = &acc[0][0][0];
#pragma unroll
            for (int j = 0; j < 16; j++) {
                asm volatile("st.shared.v4.b32 [%0], {%1,%2,%3,%4};" ::
                    "r"(part + j * 16),
                    "r"(__float_as_uint(pa[4 * j])), "r"(__float_as_uint(pa[4 * j + 1])),
                    "r"(__float_as_uint(pa[4 * j + 2])), "r"(__float_as_uint(pa[4 * j + 3]))
                    : "memory");
            }
        }
        __syncthreads();  // (2) partials visible
        if (km == 0) {
            float prt[64];
#pragma unroll
            for (int j = 0; j < 16; j++) {
                uint32_t r0w, r1w, r2w, r3w;
                asm volatile("ld.shared.v4.b32 {%0,%1,%2,%3}, [%4];"
                    : "=r"(r0w), "=r"(r1w), "=r"(r2w), "=r"(r3w) : "r"(part + j * 16));
                prt[4 * j] = __uint_as_float(r0w);   prt[4 * j + 1] = __uint_as_float(r1w);
                prt[4 * j + 2] = __uint_as_float(r2w); prt[4 * j + 3] = __uint_as_float(r3w);
            }
            const float* pa = &acc[0][0][0];
#pragma unroll
            for (int mt = 0; mt < 2; mt++) {
#pragma unroll
                for (int nt = 0; nt < 8; nt++) {
                    int base = (mt * 8 + nt) * 4;
                    int row = m0 + wm * 32 + mt * 16 + g;
                    int col = wn * 64 + nt * 8 + 2 * q;
                    float2 v0 = make_float2((pa[base] + prt[base]) * O_SCALE,
                                            (pa[base + 1] + prt[base + 1]) * O_SCALE);
                    float2 v1 = make_float2((pa[base + 2] + prt[base + 2]) * O_SCALE,
                                            (pa[base + 3] + prt[base + 3]) * O_SCALE);
                    *reinterpret_cast<float2*>(out + (size_t)row * HID + col) = v0;
                    *reinterpret_cast<float2*>(out + (size_t)(row + 8) * HID + col) = v1;
                }
            }
        }
    }
}

// ---------------------------------------------------------------------------
// launch
// ---------------------------------------------------------------------------
extern "C" void kernel_launch(void* const* d_in, const int* in_sizes, int n_in,
                              void* d_out, int out_size) {
    const float* x = nullptr;
    const float* G = nullptr;
    const float* W = nullptr;
    const float* b = nullptr;
    bool g_set = false;
    for (int i = 0; i < n_in; i++) {
        int sz = in_sizes[i];
        if (sz == NNODE * INDIM)       x = (const float*)d_in[i];
        else if (sz == NNODE * NNODE)  { if (!g_set) { G = (const float*)d_in[i]; g_set = true; } }
        else if (sz == HID * INDIM)    W = (const float*)d_in[i];
        else if (sz == HID)            b = (const float*)d_in[i];
    }
    if (!x && n_in > 0) x = (const float*)d_in[0];
    if (!G && n_in > 1) G = (const float*)d_in[1];
    if (!W && n_in > 3) W = (const float*)d_in[3];
    if (!b && n_in > 4) b = (const float*)d_in[4];

    ht_kernel<<<NNODE / 16, 128>>>(x, W, b);

    cudaFuncSetAttribute(gemm_kernel, cudaFuncAttributeMaxDynamicSharedMemorySize, SMEM_BYTES);
    gemm_kernel<<<NNODE / 64, 512, SMEM_BYTES>>>(G, (float*)d_out);
}

// round 7
// speedup vs baseline: 2.6273x; 1.4869x over previous
#include <cuda_runtime.h>
#include <cuda_fp16.h>
#include <cstdint>

#define NNODE 8192
#define INDIM 256
#define HID   128

__device__ __half g_Ht16[HID * NNODE];
__device__ float  g_part[NNODE * HID];   // khalf=1 partial

// ---------------------------------------------------------------------------
// helpers
// ---------------------------------------------------------------------------
__device__ __forceinline__ void mbar_init(uint32_t a, uint32_t n) {
    asm volatile("mbarrier.init.shared.b64 [%0], %1;" :: "r"(a), "r"(n) : "memory");
}
__device__ __forceinline__ void mbar_arrive(uint32_t a) {
    asm volatile("mbarrier.arrive.release.cta.shared::cta.b64 _, [%0];" :: "r"(a) : "memory");
}
__device__ __forceinline__ void mbar_wait(uint32_t a, uint32_t parity) {
    asm volatile(
        "{\n\t.reg .pred P;\n\t"
        "WL_%=:\n\t"
        "mbarrier.try_wait.parity.acquire.cta.shared::cta.b64 P, [%0], %1, 0x989680;\n\t"
        "@P bra.uni WD_%=;\n\t"
        "bra.uni WL_%=;\n\t"
        "WD_%=:\n\t}"
        :: "r"(a), "r"(parity) : "memory");
}
__device__ __forceinline__ void cp_async16(uint32_t smem_dst, const void* gmem_src) {
    asm volatile("cp.async.cg.shared.global [%0], [%1], 16;" :: "r"(smem_dst), "l"(gmem_src));
}
__device__ __forceinline__ void ldsm_x4(uint32_t* r, uint32_t addr) {
    asm volatile("ldmatrix.sync.aligned.m8n8.x4.shared.b16 {%0,%1,%2,%3}, [%4];"
        : "=r"(r[0]), "=r"(r[1]), "=r"(r[2]), "=r"(r[3]) : "r"(addr));
}
__device__ __forceinline__ void mma16816(float* d, const uint32_t* a, const uint32_t* bfr) {
    asm volatile(
        "mma.sync.aligned.m16n8k16.row.col.f32.f16.f16.f32 "
        "{%0,%1,%2,%3}, {%4,%5,%6,%7}, {%8,%9}, {%0,%1,%2,%3};"
        : "+f"(d[0]), "+f"(d[1]), "+f"(d[2]), "+f"(d[3])
        : "r"(a[0]), "r"(a[1]), "r"(a[2]), "r"(a[3]), "r"(bfr[0]), "r"(bfr[1]));
}

// ---------------------------------------------------------------------------
// Kernel 1: Ht16[c][j] = fp16( sum_d W[c,d]*x[j,d] + b[c] )
//   256 threads: c = tid&127, jh = tid>>7; 32 nodes / block.
// ---------------------------------------------------------------------------
__global__ __launch_bounds__(256) void ht_kernel(const float* __restrict__ x,
                                                 const float* __restrict__ W,
                                                 const float* __restrict__ b) {
    __shared__ float4 xs[32][64];
    const int tid = threadIdx.x;
    const int c   = tid & 127;
    const int jh  = tid >> 7;
    const int j0  = blockIdx.x * 32;

    const float4* xg = reinterpret_cast<const float4*>(x + (size_t)j0 * INDIM);
#pragma unroll
    for (int t = 0; t < 8; t++) {
        int idx = tid + t * 256;            // 0..2047
        int jj = idx >> 6, d4 = idx & 63;
        xs[jj][d4] = xg[jj * 64 + d4];
    }
    __syncthreads();

    float acc[16];
#pragma unroll
    for (int jj = 0; jj < 16; jj++) acc[jj] = 0.f;

    const float4* wg = reinterpret_cast<const float4*>(W + (size_t)c * INDIM);
    const int jb = jh * 16;
#pragma unroll 1
    for (int dc = 0; dc < 64; dc += 8) {
        float4 wb[8];
#pragma unroll
        for (int i = 0; i < 8; i++) wb[i] = __ldg(wg + dc + i);
#pragma unroll
        for (int i = 0; i < 8; i++) {
            float4 w4 = wb[i];
#pragma unroll
            for (int jj = 0; jj < 16; jj++) {
                float4 x4 = xs[jb + jj][dc + i];
                acc[jj] += w4.x * x4.x;
                acc[jj] += w4.y * x4.y;
                acc[jj] += w4.z * x4.z;
                acc[jj] += w4.w * x4.w;
            }
        }
    }

    const float bc = b[c];
    uint32_t hh[8];
#pragma unroll
    for (int j = 0; j < 8; j++) {
        __half2 h = __floats2half2_rn(acc[2 * j] + bc, acc[2 * j + 1] + bc);
        hh[j] = *reinterpret_cast<uint32_t*>(&h);
    }
    uint4* dst = reinterpret_cast<uint4*>(g_Ht16 + (size_t)c * NNODE + j0 + jb);
    dst[0] = make_uint4(hh[0], hh[1], hh[2], hh[3]);
    dst[1] = make_uint4(hh[4], hh[5], hh[6], hh[7]);
}

// ---------------------------------------------------------------------------
// Kernel 2: out = G @ H. Grid (128 mtiles, 2 khalves). 512 thr, 2 CTAs/SM.
//   M=64, N=128, K=4096/CTA, KT=64, S=4 ring.
//   warps 0-7 producers; warps 8-15 consumers (2Mx4N warp grid, ldmatrix).
// ---------------------------------------------------------------------------
static constexpr int S      = 4;
static constexpr int KT     = 64;
static constexpr int KHALF  = NNODE / 2;       // 4096
static constexpr int NS     = KHALF / KT;      // 64
static constexpr int RSA    = 144;
static constexpr int RSB    = 144;
static constexpr int A_SM   = 64 * RSA;        // 9216
static constexpr int B_SM   = 128 * RSB;       // 18432
static constexpr int STAGE  = A_SM + B_SM;     // 27648
static constexpr int TILE0  = 1024;
static constexpr int SMEM_BYTES = TILE0 + S * STAGE;  // 111616
#define A_SCALE 1024.0f
#define O_SCALE (1.0f / 1024.0f)

__global__ void __launch_bounds__(512, 2) gemm_kernel(const float* __restrict__ G,
                                                      float* __restrict__ out) {
    extern __shared__ char smem[];
    const uint32_t sb     = (uint32_t)__cvta_generic_to_shared(smem);
    const uint32_t full0  = sb;
    const uint32_t empty0 = sb + 64;
    const uint32_t tiles  = sb + TILE0;

    const int tid   = threadIdx.x;
    const int wid   = tid >> 5, lane = tid & 31;
    const int m0    = blockIdx.x * 64;
    const int khalf = blockIdx.y;
    const int k0    = khalf * KHALF;

    if (tid == 0) {
#pragma unroll
        for (int s = 0; s < S; s++) {
            mbar_init(full0 + s * 8, 8);
            mbar_init(empty0 + s * 8, 8);
        }
    }
    __syncthreads();

    if (wid < 8) {
        // ============ producers ============
        const int r0 = tid >> 4, c16 = tid & 15;       // A map
        const int br0 = tid >> 3, c8 = tid & 7;        // B map
        const float4* a_src = reinterpret_cast<const float4*>(
            G + (size_t)(m0 + r0) * NNODE + k0) + c16;
        const __half* b_src = g_Ht16 + (size_t)br0 * NNODE + k0 + c8 * 8;
        const uint32_t a_dst = (uint32_t)(r0 * RSA + c16 * 8);
        const uint32_t b_dst = (uint32_t)(A_SM + br0 * RSB + c8 * 16);

        float4 buf[2][4];
#pragma unroll
        for (int j = 0; j < 2; j++)
#pragma unroll
            for (int i = 0; i < 4; i++)
                buf[j][i] = __ldcs(a_src + (size_t)i * 4 * NNODE + j * 16);

        int aslot = 0;
        for (int s = 0; s < NS; s++) {
            const int slot = s & 3, lap = s >> 2;
            if (lap > 0) mbar_wait(empty0 + slot * 8, (lap - 1) & 1);
            const uint32_t st = tiles + slot * STAGE;
            // B cp.async (rows br0+32i)
#pragma unroll
            for (int i = 0; i < 4; i++)
                cp_async16(st + b_dst + i * (32 * RSB), b_src + (size_t)i * 32 * NNODE + s * KT);
            asm volatile("cp.async.commit_group;" ::: "memory");
            // A cvt + STS from depth-2 buffer (rows r0+16i)
            const int ib = s & 1;
#pragma unroll
            for (int i = 0; i < 4; i++) {
                float4 v = buf[ib][i];
                __half2 h0 = __floats2half2_rn(v.x * A_SCALE, v.y * A_SCALE);
                __half2 h1 = __floats2half2_rn(v.z * A_SCALE, v.w * A_SCALE);
                asm volatile("st.shared.v2.b32 [%0], {%1,%2};" ::
                    "r"(st + a_dst + i * (16 * RSA)),
                    "r"(*(uint32_t*)&h0), "r"(*(uint32_t*)&h1) : "memory");
            }
            // prefetch A for stage s+2
            if (s + 2 < NS) {
#pragma unroll
                for (int i = 0; i < 4; i++)
                    buf[ib][i] = __ldcs(a_src + (size_t)i * 4 * NNODE + (s + 2) * 16);
            }
            // lagged full-arrival for stage s-2 (elected)
            if (s >= 2) {
                asm volatile("cp.async.wait_group 2;" ::: "memory");
                __syncwarp();
                if (lane == 0) mbar_arrive(full0 + aslot * 8);
                if (++aslot == S) aslot = 0;
            }
        }
        asm volatile("cp.async.wait_group 0;" ::: "memory");
        __syncwarp();
        if (lane == 0) {
            mbar_arrive(full0 + aslot * 8);
            int a2 = aslot + 1; if (a2 == S) a2 = 0;
            mbar_arrive(full0 + a2 * 8);
        }
    } else {
        // ============ consumers ============
        const int cw = wid - 8;
        const int wm = cw >> 2, wn = cw & 3;   // 2(M) x 4(N), warp tile 32x32
        // ldmatrix lane address offsets (TN layout, both operands K-contiguous)
        const uint32_t a_lo = (uint32_t)((lane & 15) * RSA + (lane >> 4) * 16);
        const uint32_t b_lo = (uint32_t)((lane & 7) * RSB + ((lane >> 3) & 1) * 16
                                         + (lane >> 4) * (8 * RSB));
        const uint32_t a_base = tiles + wm * (32 * RSA) + a_lo;
        const uint32_t b_base = tiles + A_SM + wn * (32 * RSB) + b_lo;

        float acc[2][4][4];
#pragma unroll
        for (int mt = 0; mt < 2; mt++)
#pragma unroll
            for (int nt = 0; nt < 4; nt++)
#pragma unroll
                for (int i = 0; i < 4; i++) acc[mt][nt][i] = 0.f;

        for (int s = 0; s < NS; s++) {
            const int slot = s & 3;
            mbar_wait(full0 + slot * 8, (s >> 2) & 1);
            const uint32_t soff = (uint32_t)(slot * STAGE);
#pragma unroll
            for (int kc = 0; kc < 4; kc++) {
                const uint32_t kb = kc * 32;
                uint32_t af[2][4];
                ldsm_x4(af[0], a_base + soff + kb);
                ldsm_x4(af[1], a_base + soff + 16 * RSA + kb);
#pragma unroll
                for (int np = 0; np < 2; np++) {
                    uint32_t bf[4];
                    ldsm_x4(bf, b_base + soff + np * (16 * RSB) + kb);
                    mma16816(acc[0][2 * np], af[0], bf);
                    mma16816(acc[1][2 * np], af[1], bf);
                    mma16816(acc[0][2 * np + 1], af[0], bf + 2);
                    mma16816(acc[1][2 * np + 1], af[1], bf + 2);
                }
            }
            __syncwarp();
            if (lane == 0) mbar_arrive(empty0 + slot * 8);
        }

        // ---- epilogue (partial per khalf) ----
        float* dst = khalf ? g_part : out;
        const int g = lane >> 2, q = lane & 3;
#pragma unroll
        for (int mt = 0; mt < 2; mt++) {
#pragma unroll
            for (int nt = 0; nt < 4; nt++) {
                int row = m0 + wm * 32 + mt * 16 + g;
                int col = wn * 32 + nt * 8 + 2 * q;
                float2 v0 = make_float2(acc[mt][nt][0] * O_SCALE, acc[mt][nt][1] * O_SCALE);
                float2 v1 = make_float2(acc[mt][nt][2] * O_SCALE, acc[mt][nt][3] * O_SCALE);
                *reinterpret_cast<float2*>(dst + (size_t)row * HID + col) = v0;
                *reinterpret_cast<float2*>(dst + (size_t)(row + 8) * HID + col) = v1;
            }
        }
    }
}

// ---------------------------------------------------------------------------
// Kernel 3: out += g_part
// ---------------------------------------------------------------------------
__global__ __launch_bounds__(256) void reduce_kernel(float* __restrict__ out) {
    int i = blockIdx.x * 256 + threadIdx.x;
    float4* o = reinterpret_cast<float4*>(out) + i;
    const float4* p = reinterpret_cast<const float4*>(g_part) + i;
    float4 a = *o, bb = *p;
    a.x += bb.x; a.y += bb.y; a.z += bb.z; a.w += bb.w;
    *o = a;
}

// ---------------------------------------------------------------------------
// launch
// ---------------------------------------------------------------------------
extern "C" void kernel_launch(void* const* d_in, const int* in_sizes, int n_in,
                              void* d_out, int out_size) {
    const float* x = nullptr;
    const float* G = nullptr;
    const float* W = nullptr;
    const float* b = nullptr;
    bool g_set = false;
    for (int i = 0; i < n_in; i++) {
        int sz = in_sizes[i];
        if (sz == NNODE * INDIM)       x = (const float*)d_in[i];
        else if (sz == NNODE * NNODE)  { if (!g_set) { G = (const float*)d_in[i]; g_set = true; } }
        else if (sz == HID * INDIM)    W = (const float*)d_in[i];
        else if (sz == HID)            b = (const float*)d_in[i];
    }
    if (!x && n_in > 0) x = (const float*)d_in[0];
    if (!G && n_in > 1) G = (const float*)d_in[1];
    if (!W && n_in > 3) W = (const float*)d_in[3];
    if (!b && n_in > 4) b = (const float*)d_in[4];

    ht_kernel<<<NNODE / 32, 256>>>(x, W, b);

    cudaFuncSetAttribute(gemm_kernel, cudaFuncAttributeMaxDynamicSharedMemorySize, SMEM_BYTES);
    gemm_kernel<<<dim3(NNODE / 64, 2), 512, SMEM_BYTES>>>(G, (float*)d_out);

    reduce_kernel<<<(NNODE * HID / 4) / 256, 256>>>((float*)d_out);
}

// round 9
// speedup vs baseline: 3.5182x; 1.3391x over previous
#include <cuda_runtime.h>
#include <cuda_fp16.h>
#include <cstdint>

#define NNODE 8192
#define INDIM 256
#define HID   128

__device__ __half g_Ht16[HID * NNODE];
__device__ float  g_part[NNODE * HID];   // khalf=1 partial

// ---------------------------------------------------------------------------
// helpers
// ---------------------------------------------------------------------------
__device__ __forceinline__ void mbar_init(uint32_t a, uint32_t n) {
    asm volatile("mbarrier.init.shared.b64 [%0], %1;" :: "r"(a), "r"(n) : "memory");
}
__device__ __forceinline__ void mbar_arrive(uint32_t a) {
    asm volatile("mbarrier.arrive.release.cta.shared::cta.b64 _, [%0];" :: "r"(a) : "memory");
}
__device__ __forceinline__ void mbar_wait(uint32_t a, uint32_t parity) {
    asm volatile(
        "{\n\t.reg .pred P;\n\t"
        "WL_%=:\n\t"
        "mbarrier.try_wait.parity.acquire.cta.shared::cta.b64 P, [%0], %1, 0x989680;\n\t"
        "@P bra.uni WD_%=;\n\t"
        "bra.uni WL_%=;\n\t"
        "WD_%=:\n\t}"
        :: "r"(a), "r"(parity) : "memory");
}
__device__ __forceinline__ void cp_async16(uint32_t smem_dst, const void* gmem_src) {
    asm volatile("cp.async.cg.shared.global [%0], [%1], 16;" :: "r"(smem_dst), "l"(gmem_src));
}
__device__ __forceinline__ void ldsm_x4(uint32_t* r, uint32_t addr) {
    asm volatile("ldmatrix.sync.aligned.m8n8.x4.shared.b16 {%0,%1,%2,%3}, [%4];"
        : "=r"(r[0]), "=r"(r[1]), "=r"(r[2]), "=r"(r[3]) : "r"(addr));
}
__device__ __forceinline__ void mma16816(float* d, const uint32_t* a, const uint32_t* bfr) {
    asm volatile(
        "mma.sync.aligned.m16n8k16.row.col.f32.f16.f16.f32 "
        "{%0,%1,%2,%3}, {%4,%5,%6,%7}, {%8,%9}, {%0,%1,%2,%3};"
        : "+f"(d[0]), "+f"(d[1]), "+f"(d[2]), "+f"(d[3])
        : "r"(a[0]), "r"(a[1]), "r"(a[2]), "r"(a[3]), "r"(bfr[0]), "r"(bfr[1]));
}

// ---------------------------------------------------------------------------
// Kernel 1 (tensor-core): Ht16 = fp16( W @ x^T + b ), per CTA M=128(c) N=64(j) K=256
//   A=W (k-major), B=x (k-major), both fp16 in smem; W scaled x32.
// ---------------------------------------------------------------------------
static constexpr int H_RS    = 528;              // smem row stride (256 fp16 + pad)
static constexpr int H_SW    = 0;                // W tile: 128 x 528
static constexpr int H_SX    = 128 * H_RS;       // 67584: x tile 64 x 528
static constexpr int H_SB    = H_SX + 64 * H_RS; // 101376: bias 128 floats
static constexpr int H_SMEM  = H_SB + 512;       // 101888
static constexpr int H_TRS   = 144;              // transpose area stride (64 fp16 + pad)
#define W_SCALE 32.0f
#define W_INV   (1.0f / 32.0f)

__global__ void __launch_bounds__(256, 1) ht_kernel(const float* __restrict__ x,
                                                    const float* __restrict__ W,
                                                    const float* __restrict__ b) {
    extern __shared__ char hsm[];
    const uint32_t sm = (uint32_t)__cvta_generic_to_shared(hsm);
    const int tid = threadIdx.x;
    const int wid = tid >> 5, lane = tid & 31;
    const int j0  = blockIdx.x * 64;

    // ---- load + convert W (x32) : 8192 float4 chunks ----
    const float4* wg = reinterpret_cast<const float4*>(W);
#pragma unroll
    for (int i = 0; i < 32; i++) {
        int idx = tid + i * 256;                 // 0..8191
        int row = idx >> 6, c4 = idx & 63;
        float4 v = __ldg(wg + idx);
        __half2 h0 = __floats2half2_rn(v.x * W_SCALE, v.y * W_SCALE);
        __half2 h1 = __floats2half2_rn(v.z * W_SCALE, v.w * W_SCALE);
        asm volatile("st.shared.v2.b32 [%0], {%1,%2};" ::
            "r"(sm + H_SW + row * H_RS + c4 * 8),
            "r"(*(uint32_t*)&h0), "r"(*(uint32_t*)&h1) : "memory");
    }
    // ---- load + convert x tile : 4096 float4 chunks ----
    const float4* xg = reinterpret_cast<const float4*>(x + (size_t)j0 * INDIM);
#pragma unroll
    for (int i = 0; i < 16; i++) {
        int idx = tid + i * 256;                 // 0..4095
        int row = idx >> 6, c4 = idx & 63;
        float4 v = __ldg(xg + idx);
        __half2 h0 = __floats2half2_rn(v.x, v.y);
        __half2 h1 = __floats2half2_rn(v.z, v.w);
        asm volatile("st.shared.v2.b32 [%0], {%1,%2};" ::
            "r"(sm + H_SX + row * H_RS + c4 * 8),
            "r"(*(uint32_t*)&h0), "r"(*(uint32_t*)&h1) : "memory");
    }
    if (tid < 128)
        reinterpret_cast<float*>(hsm + H_SB)[tid] = b[tid];
    __syncthreads();

    // ---- MMA: warp grid 4(M=c) x 2(N=j), warp tile 32x32 ----
    const int wm = wid >> 1, wn = wid & 1;
    const int g = lane >> 2, q = lane & 3;
    const uint32_t a_lo = (uint32_t)((lane & 15) * H_RS + (lane >> 4) * 16);
    const uint32_t b_lo = (uint32_t)((lane & 7) * H_RS + ((lane >> 3) & 1) * 16
                                     + (lane >> 4) * (8 * H_RS));
    const uint32_t a_base = sm + H_SW + wm * (32 * H_RS) + a_lo;
    const uint32_t b_base = sm + H_SX + wn * (32 * H_RS) + b_lo;

    float acc[2][4][4];
#pragma unroll
    for (int mt = 0; mt < 2; mt++)
#pragma unroll
        for (int nt = 0; nt < 4; nt++)
#pragma unroll
            for (int i = 0; i < 4; i++) acc[mt][nt][i] = 0.f;

#pragma unroll
    for (int kc = 0; kc < 16; kc++) {
        const uint32_t kb = kc * 32;
        uint32_t af[2][4];
        ldsm_x4(af[0], a_base + kb);
        ldsm_x4(af[1], a_base + 16 * H_RS + kb);
#pragma unroll
        for (int np = 0; np < 2; np++) {
            uint32_t bf[4];
            ldsm_x4(bf, b_base + np * (16 * H_RS) + kb);
            mma16816(acc[0][2 * np], af[0], bf);
            mma16816(acc[1][2 * np], af[1], bf);
            mma16816(acc[0][2 * np + 1], af[0], bf + 2);
            mma16816(acc[1][2 * np + 1], af[1], bf + 2);
        }
    }
    __syncthreads();   // all ldsm done before overwriting W area with transpose

    // ---- epilogue: h = acc/32 + b[c]; write fp16 into transpose area [c][j] ----
    const float* bs = reinterpret_cast<const float*>(hsm + H_SB);
#pragma unroll
    for (int mt = 0; mt < 2; mt++) {
        int c0 = wm * 32 + mt * 16 + g;
        float b0 = bs[c0], b1 = bs[c0 + 8];
#pragma unroll
        for (int nt = 0; nt < 4; nt++) {
            int j = wn * 32 + nt * 8 + 2 * q;
            __half2 h0 = __floats2half2_rn(fmaf(acc[mt][nt][0], W_INV, b0),
                                           fmaf(acc[mt][nt][1], W_INV, b0));
            __half2 h1 = __floats2half2_rn(fmaf(acc[mt][nt][2], W_INV, b1),
                                           fmaf(acc[mt][nt][3], W_INV, b1));
            asm volatile("st.shared.b32 [%0], %1;" ::
                "r"(sm + c0 * H_TRS + j * 2), "r"(*(uint32_t*)&h0) : "memory");
            asm volatile("st.shared.b32 [%0], %1;" ::
                "r"(sm + (c0 + 8) * H_TRS + j * 2), "r"(*(uint32_t*)&h1) : "memory");
        }
    }
    __syncthreads();

    // ---- coalesced store: 128 rows x 128 B ----
#pragma unroll
    for (int i = 0; i < 4; i++) {
        int idx = tid + i * 256;                 // 0..1023
        int row = idx >> 3, c16 = idx & 7;
        uint32_t r0, r1, r2, r3;
        asm volatile("ld.shared.v4.b32 {%0,%1,%2,%3}, [%4];"
            : "=r"(r0), "=r"(r1), "=r"(r2), "=r"(r3)
            : "r"(sm + row * H_TRS + c16 * 16));
        *reinterpret_cast<uint4*>(g_Ht16 + (size_t)row * NNODE + j0 + c16 * 8) =
            make_uint4(r0, r1, r2, r3);
    }
}

// ---------------------------------------------------------------------------
// Kernel 2: out = G @ H. Grid (128 mtiles, 2 khalves). 512 thr, 2 CTAs/SM.
//   (unchanged from round 7 — verified 2-CTA/SM warp-specialized pipeline)
// ---------------------------------------------------------------------------
static constexpr int S      = 4;
static constexpr int KT     = 64;
static constexpr int KHALF  = NNODE / 2;       // 4096
static constexpr int NS     = KHALF / KT;      // 64
static constexpr int RSA    = 144;
static constexpr int RSB    = 144;
static constexpr int A_SM   = 64 * RSA;        // 9216
static constexpr int B_SM   = 128 * RSB;       // 18432
static constexpr int STAGE  = A_SM + B_SM;     // 27648
static constexpr int TILE0  = 1024;
static constexpr int SMEM_BYTES = TILE0 + S * STAGE;  // 111616
#define A_SCALE 1024.0f
#define O_SCALE (1.0f / 1024.0f)

__global__ void __launch_bounds__(512, 2) gemm_kernel(const float* __restrict__ G,
                                                      float* __restrict__ out) {
    extern __shared__ char smem[];
    const uint32_t sb     = (uint32_t)__cvta_generic_to_shared(smem);
    const uint32_t full0  = sb;
    const uint32_t empty0 = sb + 64;
    const uint32_t tiles  = sb + TILE0;

    const int tid   = threadIdx.x;
    const int wid   = tid >> 5, lane = tid & 31;
    const int m0    = blockIdx.x * 64;
    const int khalf = blockIdx.y;
    const int k0    = khalf * KHALF;

    if (tid == 0) {
#pragma unroll
        for (int s = 0; s < S; s++) {
            mbar_init(full0 + s * 8, 8);
            mbar_init(empty0 + s * 8, 8);
        }
    }
    __syncthreads();

    if (wid < 8) {
        // ============ producers ============
        const int r0 = tid >> 4, c16 = tid & 15;       // A map
        const int br0 = tid >> 3, c8 = tid & 7;        // B map
        const float4* a_src = reinterpret_cast<const float4*>(
            G + (size_t)(m0 + r0) * NNODE + k0) + c16;
        const __half* b_src = g_Ht16 + (size_t)br0 * NNODE + k0 + c8 * 8;
        const uint32_t a_dst = (uint32_t)(r0 * RSA + c16 * 8);
        const uint32_t b_dst = (uint32_t)(A_SM + br0 * RSB + c8 * 16);

        float4 buf[2][4];
#pragma unroll
        for (int j = 0; j < 2; j++)
#pragma unroll
            for (int i = 0; i < 4; i++)
                buf[j][i] = __ldcs(a_src + (size_t)i * 4 * NNODE + j * 16);

        int aslot = 0;
        for (int s = 0; s < NS; s++) {
            const int slot = s & 3, lap = s >> 2;
            if (lap > 0) mbar_wait(empty0 + slot * 8, (lap - 1) & 1);
            const uint32_t st = tiles + slot * STAGE;
            // B cp.async (rows br0+32i)
#pragma unroll
            for (int i = 0; i < 4; i++)
                cp_async16(st + b_dst + i * (32 * RSB), b_src + (size_t)i * 32 * NNODE + s * KT);
            asm volatile("cp.async.commit_group;" ::: "memory");
            // A cvt + STS from depth-2 buffer (rows r0+16i)
            const int ib = s & 1;
#pragma unroll
            for (int i = 0; i < 4; i++) {
                float4 v = buf[ib][i];
                __half2 h0 = __floats2half2_rn(v.x * A_SCALE, v.y * A_SCALE);
                __half2 h1 = __floats2half2_rn(v.z * A_SCALE, v.w * A_SCALE);
                asm volatile("st.shared.v2.b32 [%0], {%1,%2};" ::
                    "r"(st + a_dst + i * (16 * RSA)),
                    "r"(*(uint32_t*)&h0), "r"(*(uint32_t*)&h1) : "memory");
            }
            // prefetch A for stage s+2
            if (s + 2 < NS) {
#pragma unroll
                for (int i = 0; i < 4; i++)
                    buf[ib][i] = __ldcs(a_src + (size_t)i * 4 * NNODE + (s + 2) * 16);
            }
            // lagged full-arrival for stage s-2 (elected)
            if (s >= 2) {
                asm volatile("cp.async.wait_group 2;" ::: "memory");
                __syncwarp();
                if (lane == 0) mbar_arrive(full0 + aslot * 8);
                if (++aslot == S) aslot = 0;
            }
        }
        asm volatile("cp.async.wait_group 0;" ::: "memory");
        __syncwarp();
        if (lane == 0) {
            mbar_arrive(full0 + aslot * 8);
            int a2 = aslot + 1; if (a2 == S) a2 = 0;
            mbar_arrive(full0 + a2 * 8);
        }
    } else {
        // ============ consumers ============
        const int cw = wid - 8;
        const int wm = cw >> 2, wn = cw & 3;   // 2(M) x 4(N), warp tile 32x32
        const uint32_t a_lo = (uint32_t)((lane & 15) * RSA + (lane >> 4) * 16);
        const uint32_t b_lo = (uint32_t)((lane & 7) * RSB + ((lane >> 3) & 1) * 16
                                         + (lane >> 4) * (8 * RSB));
        const uint32_t a_base = tiles + wm * (32 * RSA) + a_lo;
        const uint32_t b_base = tiles + A_SM + wn * (32 * RSB) + b_lo;

        float acc[2][4][4];
#pragma unroll
        for (int mt = 0; mt < 2; mt++)
#pragma unroll
            for (int nt = 0; nt < 4; nt++)
#pragma unroll
                for (int i = 0; i < 4; i++) acc[mt][nt][i] = 0.f;

        for (int s = 0; s < NS; s++) {
            const int slot = s & 3;
            mbar_wait(full0 + slot * 8, (s >> 2) & 1);
            const uint32_t soff = (uint32_t)(slot * STAGE);
#pragma unroll
            for (int kc = 0; kc < 4; kc++) {
                const uint32_t kb = kc * 32;
                uint32_t af[2][4];
                ldsm_x4(af[0], a_base + soff + kb);
                ldsm_x4(af[1], a_base + soff + 16 * RSA + kb);
#pragma unroll
                for (int np = 0; np < 2; np++) {
                    uint32_t bf[4];
                    ldsm_x4(bf, b_base + soff + np * (16 * RSB) + kb);
                    mma16816(acc[0][2 * np], af[0], bf);
                    mma16816(acc[1][2 * np], af[1], bf);
                    mma16816(acc[0][2 * np + 1], af[0], bf + 2);
                    mma16816(acc[1][2 * np + 1], af[1], bf + 2);
                }
            }
            __syncwarp();
            if (lane == 0) mbar_arrive(empty0 + slot * 8);
        }

        // ---- epilogue (partial per khalf) ----
        float* dst = khalf ? g_part : out;
        const int g = lane >> 2, q = lane & 3;
#pragma unroll
        for (int mt = 0; mt < 2; mt++) {
#pragma unroll
            for (int nt = 0; nt < 4; nt++) {
                int row = m0 + wm * 32 + mt * 16 + g;
                int col = wn * 32 + nt * 8 + 2 * q;
                float2 v0 = make_float2(acc[mt][nt][0] * O_SCALE, acc[mt][nt][1] * O_SCALE);
                float2 v1 = make_float2(acc[mt][nt][2] * O_SCALE, acc[mt][nt][3] * O_SCALE);
                *reinterpret_cast<float2*>(dst + (size_t)row * HID + col) = v0;
                *reinterpret_cast<float2*>(dst + (size_t)(row + 8) * HID + col) = v1;
            }
        }
    }
}

// ---------------------------------------------------------------------------
// Kernel 3: out += g_part
// ---------------------------------------------------------------------------
__global__ __launch_bounds__(256) void reduce_kernel(float* __restrict__ out) {
    int i = blockIdx.x * 256 + threadIdx.x;
    float4* o = reinterpret_cast<float4*>(out) + i;
    const float4* p = reinterpret_cast<const float4*>(g_part) + i;
    float4 a = *o, bb = *p;
    a.x += bb.x; a.y += bb.y; a.z += bb.z; a.w += bb.w;
    *o = a;
}

// ---------------------------------------------------------------------------
// launch
// ---------------------------------------------------------------------------
extern "C" void kernel_launch(void* const* d_in, const int* in_sizes, int n_in,
                              void* d_out, int out_size) {
    const float* x = nullptr;
    const float* G = nullptr;
    const float* W = nullptr;
    const float* b = nullptr;
    bool g_set = false;
    for (int i = 0; i < n_in; i++) {
        int sz = in_sizes[i];
        if (sz == NNODE * INDIM)       x = (const float*)d_in[i];
        else if (sz == NNODE * NNODE)  { if (!g_set) { G = (const float*)d_in[i]; g_set = true; } }
        else if (sz == HID * INDIM)    W = (const float*)d_in[i];
        else if (sz == HID)            b = (const float*)d_in[i];
    }
    if (!x && n_in > 0) x = (const float*)d_in[0];
    if (!G && n_in > 1) G = (const float*)d_in[1];
    if (!W && n_in > 3) W = (const float*)d_in[3];
    if (!b && n_in > 4) b = (const float*)d_in[4];

    cudaFuncSetAttribute(ht_kernel, cudaFuncAttributeMaxDynamicSharedMemorySize, H_SMEM);
    ht_kernel<<<NNODE / 64, 256, H_SMEM>>>(x, W, b);

    cudaFuncSetAttribute(gemm_kernel, cudaFuncAttributeMaxDynamicSharedMemorySize, SMEM_BYTES);
    gemm_kernel<<<dim3(NNODE / 64, 2), 512, SMEM_BYTES>>>(G, (float*)d_out);

    reduce_kernel<<<(NNODE * HID / 4) / 256, 256>>>((float*)d_out);
}